// round 1
// baseline (speedup 1.0000x reference)
#include <cuda_runtime.h>

// Haar DWT level-1 on channel 0 of x:(B=32, C=3, H=512, W=512) fp32.
// Output: (B, 4, 256, 256) fp32, order [ll, lh, hl, hh].
//
// Each thread handles one (b, i, j-pair): loads float4 from rows 2i and 2i+1
// (4 consecutive input columns = 2 output columns), computes the 4 sub-bands,
// writes float2 into each of the 4 output planes.

#define H_IN 512
#define W_IN 512
#define H_OUT 256
#define W_OUT 256
#define C_IN 3

__global__ void haar_dwt_kernel(const float* __restrict__ x,
                                float* __restrict__ out) {
    // threads: B * H_OUT * (W_OUT/2)
    int idx = blockIdx.x * blockDim.x + threadIdx.x;
    const int JP = W_OUT / 2;               // 128 column-pairs per row
    int jp = idx % JP;                      // which pair of output columns
    int i  = (idx / JP) % H_OUT;            // output row
    int b  = idx / (JP * H_OUT);            // batch

    // input: channel 0 of batch b
    const float* xp = x + (size_t)b * C_IN * H_IN * W_IN;
    int col = jp * 4;                       // 4 input columns
    const float4 top = *reinterpret_cast<const float4*>(xp + (size_t)(2 * i)     * W_IN + col);
    const float4 bot = *reinterpret_cast<const float4*>(xp + (size_t)(2 * i + 1) * W_IN + col);

    // pixel pair 0: a=top.x b=top.y c=bot.x d=bot.y
    // pixel pair 1: a=top.z b=top.w c=bot.z d=bot.w
    float2 ll, lh, hl, hh;
    {
        float a = top.x, bb = top.y, c = bot.x, d = bot.z; // placeholder fixed below
        (void)a; (void)bb; (void)c; (void)d;
    }
    {
        float a = top.x, bv = top.y, c = bot.x, d = bot.y;
        float apb = a + bv, cpd = c + d;
        float amb = a - bv, cmd = c - d;
        ll.x = (apb + cpd) * 0.5f;
        lh.x = (apb - cpd) * 0.5f;
        hl.x = (amb + cmd) * 0.5f;
        hh.x = (amb - cmd) * 0.5f;
    }
    {
        float a = top.z, bv = top.w, c = bot.z, d = bot.w;
        float apb = a + bv, cpd = c + d;
        float amb = a - bv, cmd = c - d;
        ll.y = (apb + cpd) * 0.5f;
        lh.y = (apb - cpd) * 0.5f;
        hl.y = (amb + cmd) * 0.5f;
        hh.y = (amb - cmd) * 0.5f;
    }

    const size_t plane = (size_t)H_OUT * W_OUT;             // 65536
    float* op = out + (size_t)b * 4 * plane + (size_t)i * W_OUT + 2 * jp;
    *reinterpret_cast<float2*>(op + 0 * plane) = ll;
    *reinterpret_cast<float2*>(op + 1 * plane) = lh;
    *reinterpret_cast<float2*>(op + 2 * plane) = hl;
    *reinterpret_cast<float2*>(op + 3 * plane) = hh;
}

extern "C" void kernel_launch(void* const* d_in, const int* in_sizes, int n_in,
                              void* d_out, int out_size) {
    const float* x = (const float*)d_in[0];
    float* out = (float*)d_out;

    const int B = 32;
    const int total = B * H_OUT * (W_OUT / 2);   // 1,048,576 threads
    const int threads = 256;
    const int blocks = total / threads;          // 4096
    haar_dwt_kernel<<<blocks, threads>>>(x, out);
}